// round 6
// baseline (speedup 1.0000x reference)
#include <cuda_runtime.h>
#include <math.h>

#define B_ 2
#define N_ 2048
#define H_ 16
#define NCOLS 12          // log2(N)+1
#define SCALE 0.125f      // 1/sqrt(64)
#define CHUNK 64
#define NCHUNK 32         // N_/CHUNK

// Only the 32 level-6 chunk-root nodes per (b,h) ever touch global memory.
__device__ float4 g_L6K4[B_ * H_ * NCHUNK * 16];
__device__ float4 g_L6V4[B_ * H_ * NCHUNK * 16];

// fused_attn smem row map (per tensor), 124 rows of 16 float4 (no leaves!):
//  L1: 0..31   L2: 32..47   L3: 48..55   L4: 56..59   L5: 60..61
//  L6: 62..93 (all 32 chunk roots)  L7: 94..109  L8: 110..117
//  L9: 118..121  L10: 122..123
#define ROWS_T 124

__device__ __forceinline__ float halfReduce(float v, unsigned hmask) {
    v += __shfl_xor_sync(hmask, v, 8);
    v += __shfl_xor_sync(hmask, v, 4);
    v += __shfl_xor_sync(hmask, v, 2);
    v += __shfl_xor_sync(hmask, v, 1);
    return v;
}

__device__ __forceinline__ float dot4(float4 a, float4 b) {
    return a.x * b.x + a.y * b.y + a.z * b.z + a.w * b.w;
}

// 3-way softmax parent mix; 16-lane half-warp, float4/lane.
// Exact algebra: kp = 0.5(k0+k1) => s0 + s1 = 2*ss, so s1 = 2*ss - s0.
__device__ __forceinline__ void parent_mix_f4(float4 k0, float4 k1, float4 v0, float4 v1,
                                              unsigned hmask, float4& Ko, float4& Vo)
{
    float4 kp = make_float4(0.5f * (k0.x + k1.x), 0.5f * (k0.y + k1.y),
                            0.5f * (k0.z + k1.z), 0.5f * (k0.w + k1.w));
    float4 vp = make_float4(0.5f * (v0.x + v1.x), 0.5f * (v0.y + v1.y),
                            0.5f * (v0.z + v1.z), 0.5f * (v0.w + v1.w));
    float ss = halfReduce(dot4(kp, kp), hmask) * SCALE;
    float s0 = halfReduce(dot4(kp, k0), hmask) * SCALE;
    float s1 = 2.0f * ss - s0;
    float m = fmaxf(ss, fmaxf(s0, s1));
    float es = __expf(ss - m), e0 = __expf(s0 - m), e1 = __expf(s1 - m);
    float inv = 1.0f / (es + e0 + e1 + 1e-9f);
    float ws = es * inv, w0 = e0 * inv, w1 = e1 * inv;
    Ko = make_float4(ws * kp.x + w0 * k0.x + w1 * k1.x,
                     ws * kp.y + w0 * k0.y + w1 * k1.y,
                     ws * kp.z + w0 * k0.z + w1 * k1.z,
                     ws * kp.w + w0 * k0.w + w1 * k1.w);
    Vo = make_float4(ws * vp.x + w0 * v0.x + w1 * v1.x,
                     ws * vp.y + w0 * v0.y + w1 * v1.y,
                     ws * vp.z + w0 * v0.z + w1 * v1.z,
                     ws * vp.w + w0 * v0.w + w1 * v1.w);
}

__device__ __forceinline__ void mix_rows(float4* sK, float4* sV, int cb, int pr,
                                         int c16, unsigned hmask)
{
    float4 Ko, Vo;
    parent_mix_f4(sK[cb * 16 + c16], sK[(cb + 1) * 16 + c16],
                  sV[cb * 16 + c16], sV[(cb + 1) * 16 + c16], hmask, Ko, Vo);
    sK[pr * 16 + c16] = Ko;
    sV[pr * 16 + c16] = Vo;
}

// k1: per 64-leaf chunk, build levels 1..6 (L1 straight from global leaves);
// emit ONLY the level-6 node to global. smem = L1..L5 (62 rows/tensor, 31 KB).
__global__ __launch_bounds__(512) void build_chunk_root(const float* __restrict__ K,
                                                        const float* __restrict__ V)
{
    __shared__ float4 sK[62 * 16];
    __shared__ float4 sV[62 * 16];
    int c = blockIdx.x % NCHUNK;
    int h = (blockIdx.x / NCHUNK) % H_;
    int b = blockIdx.x / (NCHUNK * H_);
    int tid = threadIdx.x, lane = tid & 31, warp = tid >> 5;
    int c16 = lane & 15;
    int halfIdx = warp * 2 + (lane >> 4);
    unsigned hmask = 0xFFFFu << (lane & 16);

    const float4* K4 = (const float4*)K;
    const float4* V4 = (const float4*)V;
    const float4* leafK = K4 + ((size_t)(b * N_ + c * CHUNK) * H_ + h) * 16;
    const float4* leafV = V4 + ((size_t)(b * N_ + c * CHUNK) * H_ + h) * 16;
    const int LS = H_ * 16;   // float4 stride between consecutive leaves

    // L1 (32 parents) from global leaf pairs.
    {
        int j = halfIdx;
        float4 Ko, Vo;
        parent_mix_f4(leafK[(2 * j) * LS + c16], leafK[(2 * j + 1) * LS + c16],
                      leafV[(2 * j) * LS + c16], leafV[(2 * j + 1) * LS + c16],
                      hmask, Ko, Vo);
        sK[j * 16 + c16] = Ko;
        sV[j * 16 + c16] = Vo;
    }
    __syncthreads();
    if (halfIdx < 16) mix_rows(sK, sV, 0 + 2 * halfIdx, 32 + halfIdx, c16, hmask);   // L2
    __syncthreads();
    if (halfIdx < 8)  mix_rows(sK, sV, 32 + 2 * halfIdx, 48 + halfIdx, c16, hmask);  // L3
    __syncthreads();
    if (halfIdx < 4)  mix_rows(sK, sV, 48 + 2 * halfIdx, 56 + halfIdx, c16, hmask);  // L4
    __syncthreads();
    if (halfIdx < 2)  mix_rows(sK, sV, 56 + 2 * halfIdx, 60 + halfIdx, c16, hmask);  // L5
    __syncthreads();
    if (halfIdx == 0) {                                                               // L6
        float4 Ko, Vo;
        parent_mix_f4(sK[60 * 16 + c16], sK[61 * 16 + c16],
                      sV[60 * 16 + c16], sV[61 * 16 + c16], hmask, Ko, Vo);
        g_L6K4[((b * H_ + h) * NCHUNK + c) * 16 + c16] = Ko;
        g_L6V4[((b * H_ + h) * NCHUNK + c) * 16 + c16] = Vo;
    }
}

// k2: fused re-build (L1..L5 from global leaves, L7..L10 from staged L6) + attention.
// Block = one 64-leaf chunk of one (b,h); 512 threads = 32 half-warps,
// 2 queries/half-warp; lvl0/lvl1 gathers from global (L1-hot), rest from smem.
__global__ __launch_bounds__(512) void fused_attn(const float* __restrict__ Q,
                                                  const float* __restrict__ K,
                                                  const float* __restrict__ V,
                                                  float* __restrict__ out)
{
    extern __shared__ float4 smem[];
    float4* sK = smem;
    float4* sV = smem + ROWS_T * 16;

    int c = blockIdx.x % NCHUNK;
    int h = (blockIdx.x / NCHUNK) % H_;
    int b = blockIdx.x / (NCHUNK * H_);
    int tid = threadIdx.x, lane = tid & 31, warp = tid >> 5;
    int c16 = lane & 15;
    int halfIdx = warp * 2 + (lane >> 4);
    unsigned hmask = 0xFFFFu << (lane & 16);

    const float4* Q4 = (const float4*)Q;
    const float4* K4 = (const float4*)K;
    const float4* V4 = (const float4*)V;
    float4* out4 = (float4*)out;

    const float4* leafK = K4 + ((size_t)(b * N_ + c * CHUNK) * H_ + h) * 16;
    const float4* leafV = V4 + ((size_t)(b * N_ + c * CHUNK) * H_ + h) * 16;
    const int LS = H_ * 16;

    // Stage the 32 level-6 nodes into rows 62..93.
    for (int i = tid; i < NCHUNK * 16; i += 512) {
        int node = i >> 4, d4 = i & 15;
        int off = ((b * H_ + h) * NCHUNK + node) * 16 + d4;
        sK[(62 + node) * 16 + d4] = g_L6K4[off];
        sV[(62 + node) * 16 + d4] = g_L6V4[off];
    }
    __syncthreads();

    // Round 1: L1 (32, children = global leaves) + L7 (16, children = L6 rows).
    for (int t = halfIdx; t < 48; t += 32) {
        if (t < 32) {
            float4 Ko, Vo;
            parent_mix_f4(leafK[(2 * t) * LS + c16], leafK[(2 * t + 1) * LS + c16],
                          leafV[(2 * t) * LS + c16], leafV[(2 * t + 1) * LS + c16],
                          hmask, Ko, Vo);
            sK[t * 16 + c16] = Ko;
            sV[t * 16 + c16] = Vo;
        } else {
            int j = t - 32;
            mix_rows(sK, sV, 62 + 2 * j, 94 + j, c16, hmask);
        }
    }
    __syncthreads();
    // Round 2: L2 (16) + L8 (8)
    if (halfIdx < 24) {
        if (halfIdx < 16) mix_rows(sK, sV, 0 + 2 * halfIdx, 32 + halfIdx, c16, hmask);
        else { int j = halfIdx - 16; mix_rows(sK, sV, 94 + 2 * j, 110 + j, c16, hmask); }
    }
    __syncthreads();
    // Round 3: L3 (8) + L9 (4)
    if (halfIdx < 12) {
        if (halfIdx < 8) mix_rows(sK, sV, 32 + 2 * halfIdx, 48 + halfIdx, c16, hmask);
        else { int j = halfIdx - 8; mix_rows(sK, sV, 110 + 2 * j, 118 + j, c16, hmask); }
    }
    __syncthreads();
    // Round 4: L4 (4) + L10 (2)
    if (halfIdx < 6) {
        if (halfIdx < 4) mix_rows(sK, sV, 48 + 2 * halfIdx, 56 + halfIdx, c16, hmask);
        else { int j = halfIdx - 4; mix_rows(sK, sV, 118 + 2 * j, 122 + j, c16, hmask); }
    }
    __syncthreads();
    // Round 5: L5 (2)
    if (halfIdx < 2) mix_rows(sK, sV, 56 + 2 * halfIdx, 60 + halfIdx, c16, hmask);
    __syncthreads();

    // ---- Attention: 2 queries per half-warp ----
    const int baseL[11] = {0, 0, 1024, 1536, 1792, 1920, 1984, 2016, 2032, 2040, 2044};
    const int rowB[11]  = {0, 0, 32, 48, 56, 60, 62, 94, 110, 118, 122};

#pragma unroll
    for (int u = 0; u < 2; u++) {
        int q = halfIdx + 32 * u;
        int n = c * CHUNK + q;

        // Levels >=2 smem rows + causal mask bits (all entries valid for N=2048).
        int row[NCOLS];
        unsigned maskbits = 0u;
        int ncur = n ^ 1;                    // lvl-1 entry: sibling leaf (global)
        if ((n & 1) == 0) maskbits |= 2u;    // pair(n) < n^1 when n even
#pragma unroll
        for (int lvl = 2; lvl < NCOLS; lvl++) {
            int pair = (ncur >> 1) + N_;
            int nnext = pair ^ 1;
            int L = lvl - 1;
            int jL = nnext - N_ - baseL[L];
            row[lvl] = rowB[L] + jL - ((L <= 5) ? (c << (6 - L)) : 0);
            if (pair < nnext) maskbits |= (1u << lvl);
            ncur = nnext;
        }

        int qbase = ((b * N_ + n) * H_ + h) * 16;
        float4 qv = Q4[qbase + c16];

        float s[NCOLS];
        s[0] = dot4(qv, leafK[q * LS + c16]);
        s[1] = dot4(qv, leafK[(q ^ 1) * LS + c16]);
#pragma unroll
        for (int l = 2; l < NCOLS; l++)
            s[l] = dot4(qv, sK[row[l] * 16 + c16]);
#pragma unroll
        for (int l = 0; l < NCOLS; l++)
            s[l] = halfReduce(s[l], hmask) * SCALE;

        float m = -INFINITY;
#pragma unroll
        for (int l = 0; l < NCOLS; l++)
            if (!((maskbits >> l) & 1u)) m = fmaxf(m, s[l]);

        float sum = 0.0f;
#pragma unroll
        for (int l = 0; l < NCOLS; l++) {
            float w = ((maskbits >> l) & 1u) ? 0.0f : __expf(s[l] - m);
            s[l] = w;
            sum += w;
        }
        float inv = 1.0f / sum;

        float4 o = make_float4(0.f, 0.f, 0.f, 0.f);
        {
            float4 v0 = leafV[q * LS + c16];
            float4 v1 = leafV[(q ^ 1) * LS + c16];
            o.x = s[0] * v0.x + s[1] * v1.x;
            o.y = s[0] * v0.y + s[1] * v1.y;
            o.z = s[0] * v0.z + s[1] * v1.z;
            o.w = s[0] * v0.w + s[1] * v1.w;
        }
#pragma unroll
        for (int l = 2; l < NCOLS; l++) {
            float4 v = sV[row[l] * 16 + c16];
            o.x += s[l] * v.x;
            o.y += s[l] * v.y;
            o.z += s[l] * v.z;
            o.w += s[l] * v.w;
        }
        out4[qbase + c16] = make_float4(o.x * inv, o.y * inv, o.z * inv, o.w * inv);
    }
}

extern "C" void kernel_launch(void* const* d_in, const int* in_sizes, int n_in,
                              void* d_out, int out_size)
{
    const float* Q = (const float*)d_in[0];
    const float* K = (const float*)d_in[1];
    const float* V = (const float*)d_in[2];
    float* out = (float*)d_out;

    const int smemBytes = 2 * ROWS_T * 16 * (int)sizeof(float4);   // 63488 B
    static int attrSet = 0;
    if (!attrSet) {
        cudaFuncSetAttribute(fused_attn, cudaFuncAttributeMaxDynamicSharedMemorySize, smemBytes);
        attrSet = 1;
    }

    build_chunk_root<<<B_ * H_ * NCHUNK, 512>>>(K, V);
    fused_attn<<<B_ * H_ * NCHUNK, 512, smemBytes>>>(Q, K, V, out);
}

// round 7
// speedup vs baseline: 1.1179x; 1.1179x over previous
#include <cuda_runtime.h>
#include <math.h>

#define B_ 2
#define N_ 2048
#define H_ 16
#define NCOLS 12          // log2(N)+1
#define SCALE 0.125f      // 1/sqrt(64)
#define CHUNK 64
#define NCHUNK 32         // N_/CHUNK

// Only the 32 level-6 chunk-root nodes per (b,h) ever touch global memory.
__device__ float4 g_L6K4[B_ * H_ * NCHUNK * 16];
__device__ float4 g_L6V4[B_ * H_ * NCHUNK * 16];

// fused_attn smem row map (per tensor), 124 rows of 16 float4 (no leaves):
//  L1: 0..31   L2: 32..47   L3: 48..55   L4: 56..59   L5: 60..61
//  L6: 62..93 (all 32 chunk roots)  L7: 94..109  L8: 110..117
//  L9: 118..121  L10: 122..123
#define ROWS_T 124

__device__ __forceinline__ float halfReduce(float v, unsigned hmask) {
    v += __shfl_xor_sync(hmask, v, 8);
    v += __shfl_xor_sync(hmask, v, 4);
    v += __shfl_xor_sync(hmask, v, 2);
    v += __shfl_xor_sync(hmask, v, 1);
    return v;
}

__device__ __forceinline__ float dot4(float4 a, float4 b) {
    return a.x * b.x + a.y * b.y + a.z * b.z + a.w * b.w;
}

// 3-way softmax parent mix; 16-lane half-warp, float4/lane.
// Exact algebra: kp = 0.5(k0+k1) => s0 + s1 = 2*ss, so s1 = 2*ss - s0.
__device__ __forceinline__ void parent_mix_f4(float4 k0, float4 k1, float4 v0, float4 v1,
                                              unsigned hmask, float4& Ko, float4& Vo)
{
    float4 kp = make_float4(0.5f * (k0.x + k1.x), 0.5f * (k0.y + k1.y),
                            0.5f * (k0.z + k1.z), 0.5f * (k0.w + k1.w));
    float4 vp = make_float4(0.5f * (v0.x + v1.x), 0.5f * (v0.y + v1.y),
                            0.5f * (v0.z + v1.z), 0.5f * (v0.w + v1.w));
    float ss = halfReduce(dot4(kp, kp), hmask) * SCALE;
    float s0 = halfReduce(dot4(kp, k0), hmask) * SCALE;
    float s1 = 2.0f * ss - s0;
    float m = fmaxf(ss, fmaxf(s0, s1));
    float es = __expf(ss - m), e0 = __expf(s0 - m), e1 = __expf(s1 - m);
    float inv = 1.0f / (es + e0 + e1 + 1e-9f);
    float ws = es * inv, w0 = e0 * inv, w1 = e1 * inv;
    Ko = make_float4(ws * kp.x + w0 * k0.x + w1 * k1.x,
                     ws * kp.y + w0 * k0.y + w1 * k1.y,
                     ws * kp.z + w0 * k0.z + w1 * k1.z,
                     ws * kp.w + w0 * k0.w + w1 * k1.w);
    Vo = make_float4(ws * vp.x + w0 * v0.x + w1 * v1.x,
                     ws * vp.y + w0 * v0.y + w1 * v1.y,
                     ws * vp.z + w0 * v0.z + w1 * v1.z,
                     ws * vp.w + w0 * v0.w + w1 * v1.w);
}

__device__ __forceinline__ void mix_rows(float4* sK, float4* sV, int cb, int pr,
                                         int c16, unsigned hmask)
{
    float4 Ko, Vo;
    parent_mix_f4(sK[cb * 16 + c16], sK[(cb + 1) * 16 + c16],
                  sV[cb * 16 + c16], sV[(cb + 1) * 16 + c16], hmask, Ko, Vo);
    sK[pr * 16 + c16] = Ko;
    sV[pr * 16 + c16] = Vo;
}

// k1: per 64-leaf chunk, build levels 1..6 (L1 straight from global leaves);
// emit ONLY the level-6 node to global. smem = L1..L5 (62 rows/tensor, 31 KB).
__global__ __launch_bounds__(512, 2) void build_chunk_root(const float* __restrict__ K,
                                                           const float* __restrict__ V)
{
    __shared__ float4 sK[62 * 16];
    __shared__ float4 sV[62 * 16];
    int c = blockIdx.x % NCHUNK;
    int h = (blockIdx.x / NCHUNK) % H_;
    int b = blockIdx.x / (NCHUNK * H_);
    int tid = threadIdx.x, lane = tid & 31, warp = tid >> 5;
    int c16 = lane & 15;
    int halfIdx = warp * 2 + (lane >> 4);
    unsigned hmask = 0xFFFFu << (lane & 16);

    const float4* K4 = (const float4*)K;
    const float4* V4 = (const float4*)V;
    const float4* leafK = K4 + ((size_t)(b * N_ + c * CHUNK) * H_ + h) * 16;
    const float4* leafV = V4 + ((size_t)(b * N_ + c * CHUNK) * H_ + h) * 16;
    const int LS = H_ * 16;   // float4 stride between consecutive leaves

    // L1 (32 parents) from global leaf pairs.
    {
        int j = halfIdx;
        float4 Ko, Vo;
        parent_mix_f4(leafK[(2 * j) * LS + c16], leafK[(2 * j + 1) * LS + c16],
                      leafV[(2 * j) * LS + c16], leafV[(2 * j + 1) * LS + c16],
                      hmask, Ko, Vo);
        sK[j * 16 + c16] = Ko;
        sV[j * 16 + c16] = Vo;
    }
    __syncthreads();
    if (halfIdx < 16) mix_rows(sK, sV, 0 + 2 * halfIdx, 32 + halfIdx, c16, hmask);   // L2
    __syncthreads();
    if (halfIdx < 8)  mix_rows(sK, sV, 32 + 2 * halfIdx, 48 + halfIdx, c16, hmask);  // L3
    __syncthreads();
    if (halfIdx < 4)  mix_rows(sK, sV, 48 + 2 * halfIdx, 56 + halfIdx, c16, hmask);  // L4
    __syncthreads();
    if (halfIdx < 2)  mix_rows(sK, sV, 56 + 2 * halfIdx, 60 + halfIdx, c16, hmask);  // L5
    __syncthreads();
    if (halfIdx == 0) {                                                               // L6
        float4 Ko, Vo;
        parent_mix_f4(sK[60 * 16 + c16], sK[61 * 16 + c16],
                      sV[60 * 16 + c16], sV[61 * 16 + c16], hmask, Ko, Vo);
        g_L6K4[((b * H_ + h) * NCHUNK + c) * 16 + c16] = Ko;
        g_L6V4[((b * H_ + h) * NCHUNK + c) * 16 + c16] = Vo;
    }
}

// k2: fused re-build (L1..L5 from global leaves, L7..L10 from staged L6) + attention.
// __launch_bounds__(512, 2): cap regs at 64 so 2 blocks/SM stay resident (R6 post-
// mortem: 84 regs -> 1 block/SM -> occ 24.5% regression).
__global__ __launch_bounds__(512, 2) void fused_attn(const float* __restrict__ Q,
                                                     const float* __restrict__ K,
                                                     const float* __restrict__ V,
                                                     float* __restrict__ out)
{
    extern __shared__ float4 smem[];
    float4* sK = smem;
    float4* sV = smem + ROWS_T * 16;

    int c = blockIdx.x % NCHUNK;
    int h = (blockIdx.x / NCHUNK) % H_;
    int b = blockIdx.x / (NCHUNK * H_);
    int tid = threadIdx.x, lane = tid & 31, warp = tid >> 5;
    int c16 = lane & 15;
    int halfIdx = warp * 2 + (lane >> 4);
    unsigned hmask = 0xFFFFu << (lane & 16);

    const float4* Q4 = (const float4*)Q;
    const float4* K4 = (const float4*)K;
    const float4* V4 = (const float4*)V;
    float4* out4 = (float4*)out;

    const float4* leafK = K4 + ((size_t)(b * N_ + c * CHUNK) * H_ + h) * 16;
    const float4* leafV = V4 + ((size_t)(b * N_ + c * CHUNK) * H_ + h) * 16;
    const int LS = H_ * 16;

    // Stage the 32 level-6 nodes into rows 62..93.
    for (int i = tid; i < NCHUNK * 16; i += 512) {
        int node = i >> 4, d4 = i & 15;
        int off = ((b * H_ + h) * NCHUNK + node) * 16 + d4;
        sK[(62 + node) * 16 + d4] = g_L6K4[off];
        sV[(62 + node) * 16 + d4] = g_L6V4[off];
    }
    __syncthreads();

    // Round 1: L1 (32, children = global leaves) + L7 (16, children = L6 rows).
    for (int t = halfIdx; t < 48; t += 32) {
        if (t < 32) {
            float4 Ko, Vo;
            parent_mix_f4(leafK[(2 * t) * LS + c16], leafK[(2 * t + 1) * LS + c16],
                          leafV[(2 * t) * LS + c16], leafV[(2 * t + 1) * LS + c16],
                          hmask, Ko, Vo);
            sK[t * 16 + c16] = Ko;
            sV[t * 16 + c16] = Vo;
        } else {
            int j = t - 32;
            mix_rows(sK, sV, 62 + 2 * j, 94 + j, c16, hmask);
        }
    }
    __syncthreads();
    // Round 2: L2 (16) + L8 (8)
    if (halfIdx < 24) {
        if (halfIdx < 16) mix_rows(sK, sV, 0 + 2 * halfIdx, 32 + halfIdx, c16, hmask);
        else { int j = halfIdx - 16; mix_rows(sK, sV, 94 + 2 * j, 110 + j, c16, hmask); }
    }
    __syncthreads();
    // Round 3: L3 (8) + L9 (4)
    if (halfIdx < 12) {
        if (halfIdx < 8) mix_rows(sK, sV, 32 + 2 * halfIdx, 48 + halfIdx, c16, hmask);
        else { int j = halfIdx - 8; mix_rows(sK, sV, 110 + 2 * j, 118 + j, c16, hmask); }
    }
    __syncthreads();
    // Round 4: L4 (4) + L10 (2)
    if (halfIdx < 6) {
        if (halfIdx < 4) mix_rows(sK, sV, 48 + 2 * halfIdx, 56 + halfIdx, c16, hmask);
        else { int j = halfIdx - 4; mix_rows(sK, sV, 118 + 2 * j, 122 + j, c16, hmask); }
    }
    __syncthreads();
    // Round 5: L5 (2)
    if (halfIdx < 2) mix_rows(sK, sV, 56 + 2 * halfIdx, 60 + halfIdx, c16, hmask);
    __syncthreads();

    // ---- Attention: 2 queries per half-warp ----
    const int baseL[11] = {0, 0, 1024, 1536, 1792, 1920, 1984, 2016, 2032, 2040, 2044};
    const int rowB[11]  = {0, 0, 32, 48, 56, 60, 62, 94, 110, 118, 122};

#pragma unroll
    for (int u = 0; u < 2; u++) {
        int q = halfIdx + 32 * u;
        int n = c * CHUNK + q;

        // Levels >=2 smem rows + causal mask bits (all entries valid for N=2048).
        int row[NCOLS];
        unsigned maskbits = 0u;
        int ncur = n ^ 1;                    // lvl-1 entry: sibling leaf (global)
        if ((n & 1) == 0) maskbits |= 2u;    // pair(n) < n^1 when n even
#pragma unroll
        for (int lvl = 2; lvl < NCOLS; lvl++) {
            int pair = (ncur >> 1) + N_;
            int nnext = pair ^ 1;
            int L = lvl - 1;
            int jL = nnext - N_ - baseL[L];
            row[lvl] = rowB[L] + jL - ((L <= 5) ? (c << (6 - L)) : 0);
            if (pair < nnext) maskbits |= (1u << lvl);
            ncur = nnext;
        }

        int qbase = ((b * N_ + n) * H_ + h) * 16;
        float4 qv = Q4[qbase + c16];

        float s[NCOLS];
        s[0] = dot4(qv, leafK[q * LS + c16]);
        s[1] = dot4(qv, leafK[(q ^ 1) * LS + c16]);
#pragma unroll
        for (int l = 2; l < NCOLS; l++)
            s[l] = dot4(qv, sK[row[l] * 16 + c16]);
#pragma unroll
        for (int l = 0; l < NCOLS; l++)
            s[l] = halfReduce(s[l], hmask) * SCALE;

        float m = -INFINITY;
#pragma unroll
        for (int l = 0; l < NCOLS; l++)
            if (!((maskbits >> l) & 1u)) m = fmaxf(m, s[l]);

        float sum = 0.0f;
#pragma unroll
        for (int l = 0; l < NCOLS; l++) {
            float w = ((maskbits >> l) & 1u) ? 0.0f : __expf(s[l] - m);
            s[l] = w;
            sum += w;
        }
        float inv = 1.0f / sum;

        float4 o = make_float4(0.f, 0.f, 0.f, 0.f);
        {
            float4 v0 = leafV[q * LS + c16];
            float4 v1 = leafV[(q ^ 1) * LS + c16];
            o.x = s[0] * v0.x + s[1] * v1.x;
            o.y = s[0] * v0.y + s[1] * v1.y;
            o.z = s[0] * v0.z + s[1] * v1.z;
            o.w = s[0] * v0.w + s[1] * v1.w;
        }
#pragma unroll
        for (int l = 2; l < NCOLS; l++) {
            float4 v = sV[row[l] * 16 + c16];
            o.x += s[l] * v.x;
            o.y += s[l] * v.y;
            o.z += s[l] * v.z;
            o.w += s[l] * v.w;
        }
        out4[qbase + c16] = make_float4(o.x * inv, o.y * inv, o.z * inv, o.w * inv);
    }
}

extern "C" void kernel_launch(void* const* d_in, const int* in_sizes, int n_in,
                              void* d_out, int out_size)
{
    const float* Q = (const float*)d_in[0];
    const float* K = (const float*)d_in[1];
    const float* V = (const float*)d_in[2];
    float* out = (float*)d_out;

    const int smemBytes = 2 * ROWS_T * 16 * (int)sizeof(float4);   // 63488 B
    static int attrSet = 0;
    if (!attrSet) {
        cudaFuncSetAttribute(fused_attn, cudaFuncAttributeMaxDynamicSharedMemorySize, smemBytes);
        attrSet = 1;
    }

    build_chunk_root<<<B_ * H_ * NCHUNK, 512>>>(K, V);
    fused_attn<<<B_ * H_ * NCHUNK, 512, smemBytes>>>(Q, K, V, out);
}

// round 8
// speedup vs baseline: 1.2767x; 1.1420x over previous
#include <cuda_runtime.h>
#include <math.h>

#define B_ 2
#define N_ 2048
#define H_ 16
#define NCOLS 12          // log2(N)+1
#define SCALE 0.125f      // 1/sqrt(64)
#define CHUNK 64
#define NCHUNK 32         // N_/CHUNK

// Only the 32 level-6 chunk-root nodes per (b,h) ever touch global memory.
__device__ float4 g_L6K4[B_ * H_ * NCHUNK * 16];
__device__ float4 g_L6V4[B_ * H_ * NCHUNK * 16];

// fused_attn smem row map (per tensor), 124 rows of 16 float4 (no leaves):
//  L1: 0..31   L2: 32..47   L3: 48..55   L4: 56..59   L5: 60..61
//  L6: 62..93 (all 32 chunk roots)  L7: 94..109  L8: 110..117
//  L9: 118..121  L10: 122..123
#define ROWS_T 124

__device__ __forceinline__ float halfReduce(float v, unsigned hmask) {
    v += __shfl_xor_sync(hmask, v, 8);
    v += __shfl_xor_sync(hmask, v, 4);
    v += __shfl_xor_sync(hmask, v, 2);
    v += __shfl_xor_sync(hmask, v, 1);
    return v;
}

__device__ __forceinline__ float octReduce(float v) {
    v += __shfl_xor_sync(0xffffffffu, v, 4);
    v += __shfl_xor_sync(0xffffffffu, v, 2);
    v += __shfl_xor_sync(0xffffffffu, v, 1);
    return v;
}

__device__ __forceinline__ float dot4(float4 a, float4 b) {
    return a.x * b.x + a.y * b.y + a.z * b.z + a.w * b.w;
}

// 3-way softmax parent mix; 16-lane half-warp, float4/lane.
// Exact algebra: kp = 0.5(k0+k1) => s0 + s1 = 2*ss, so s1 = 2*ss - s0.
__device__ __forceinline__ void parent_mix_f4(float4 k0, float4 k1, float4 v0, float4 v1,
                                              unsigned hmask, float4& Ko, float4& Vo)
{
    float4 kp = make_float4(0.5f * (k0.x + k1.x), 0.5f * (k0.y + k1.y),
                            0.5f * (k0.z + k1.z), 0.5f * (k0.w + k1.w));
    float4 vp = make_float4(0.5f * (v0.x + v1.x), 0.5f * (v0.y + v1.y),
                            0.5f * (v0.z + v1.z), 0.5f * (v0.w + v1.w));
    float ss = halfReduce(dot4(kp, kp), hmask) * SCALE;
    float s0 = halfReduce(dot4(kp, k0), hmask) * SCALE;
    float s1 = 2.0f * ss - s0;
    float m = fmaxf(ss, fmaxf(s0, s1));
    float es = __expf(ss - m), e0 = __expf(s0 - m), e1 = __expf(s1 - m);
    float inv = 1.0f / (es + e0 + e1 + 1e-9f);
    float ws = es * inv, w0 = e0 * inv, w1 = e1 * inv;
    Ko = make_float4(ws * kp.x + w0 * k0.x + w1 * k1.x,
                     ws * kp.y + w0 * k0.y + w1 * k1.y,
                     ws * kp.z + w0 * k0.z + w1 * k1.z,
                     ws * kp.w + w0 * k0.w + w1 * k1.w);
    Vo = make_float4(ws * vp.x + w0 * v0.x + w1 * v1.x,
                     ws * vp.y + w0 * v0.y + w1 * v1.y,
                     ws * vp.z + w0 * v0.z + w1 * v1.z,
                     ws * vp.w + w0 * v0.w + w1 * v1.w);
}

__device__ __forceinline__ void mix_rows(float4* sK, float4* sV, int cb, int pr,
                                         int c16, unsigned hmask)
{
    float4 Ko, Vo;
    parent_mix_f4(sK[cb * 16 + c16], sK[(cb + 1) * 16 + c16],
                  sV[cb * 16 + c16], sV[(cb + 1) * 16 + c16], hmask, Ko, Vo);
    sK[pr * 16 + c16] = Ko;
    sV[pr * 16 + c16] = Vo;
}

// k1: per 64-leaf chunk, build levels 1..6 (L1 straight from global leaves);
// emit ONLY the level-6 node to global. smem = L1..L5 (62 rows/tensor, 31 KB).
__global__ __launch_bounds__(512, 2) void build_chunk_root(const float* __restrict__ K,
                                                           const float* __restrict__ V)
{
    __shared__ float4 sK[62 * 16];
    __shared__ float4 sV[62 * 16];
    int c = blockIdx.x % NCHUNK;
    int h = (blockIdx.x / NCHUNK) % H_;
    int b = blockIdx.x / (NCHUNK * H_);
    int tid = threadIdx.x, lane = tid & 31, warp = tid >> 5;
    int c16 = lane & 15;
    int halfIdx = warp * 2 + (lane >> 4);
    unsigned hmask = 0xFFFFu << (lane & 16);

    const float4* K4 = (const float4*)K;
    const float4* V4 = (const float4*)V;
    const float4* leafK = K4 + ((size_t)(b * N_ + c * CHUNK) * H_ + h) * 16;
    const float4* leafV = V4 + ((size_t)(b * N_ + c * CHUNK) * H_ + h) * 16;
    const int LS = H_ * 16;   // float4 stride between consecutive leaves

    // L1 (32 parents) from global leaf pairs.
    {
        int j = halfIdx;
        float4 Ko, Vo;
        parent_mix_f4(leafK[(2 * j) * LS + c16], leafK[(2 * j + 1) * LS + c16],
                      leafV[(2 * j) * LS + c16], leafV[(2 * j + 1) * LS + c16],
                      hmask, Ko, Vo);
        sK[j * 16 + c16] = Ko;
        sV[j * 16 + c16] = Vo;
    }
    __syncthreads();
    if (halfIdx < 16) mix_rows(sK, sV, 0 + 2 * halfIdx, 32 + halfIdx, c16, hmask);   // L2
    __syncthreads();
    if (halfIdx < 8)  mix_rows(sK, sV, 32 + 2 * halfIdx, 48 + halfIdx, c16, hmask);  // L3
    __syncthreads();
    if (halfIdx < 4)  mix_rows(sK, sV, 48 + 2 * halfIdx, 56 + halfIdx, c16, hmask);  // L4
    __syncthreads();
    if (halfIdx < 2)  mix_rows(sK, sV, 56 + 2 * halfIdx, 60 + halfIdx, c16, hmask);  // L5
    __syncthreads();
    if (halfIdx == 0) {                                                               // L6
        float4 Ko, Vo;
        parent_mix_f4(sK[60 * 16 + c16], sK[61 * 16 + c16],
                      sV[60 * 16 + c16], sV[61 * 16 + c16], hmask, Ko, Vo);
        g_L6K4[((b * H_ + h) * NCHUNK + c) * 16 + c16] = Ko;
        g_L6V4[((b * H_ + h) * NCHUNK + c) * 16 + c16] = Vo;
    }
}

// k2: fused re-build (L1..L5 from global leaves, L7..L10 from staged L6) + attention.
// Attention runs on 8-lane groups: 4 queries per warp, 3-step reductions.
__global__ __launch_bounds__(512, 2) void fused_attn(const float* __restrict__ Q,
                                                     const float* __restrict__ K,
                                                     const float* __restrict__ V,
                                                     float* __restrict__ out)
{
    extern __shared__ float4 smem[];
    float4* sK = smem;
    float4* sV = smem + ROWS_T * 16;

    int c = blockIdx.x % NCHUNK;
    int h = (blockIdx.x / NCHUNK) % H_;
    int b = blockIdx.x / (NCHUNK * H_);
    int tid = threadIdx.x, lane = tid & 31, warp = tid >> 5;
    int c16 = lane & 15;
    int halfIdx = warp * 2 + (lane >> 4);
    unsigned hmask = 0xFFFFu << (lane & 16);

    const float4* Q4 = (const float4*)Q;
    const float4* K4 = (const float4*)K;
    const float4* V4 = (const float4*)V;
    float4* out4 = (float4*)out;

    const float4* leafK = K4 + ((size_t)(b * N_ + c * CHUNK) * H_ + h) * 16;
    const float4* leafV = V4 + ((size_t)(b * N_ + c * CHUNK) * H_ + h) * 16;
    const int LS = H_ * 16;

    // Stage the 32 level-6 nodes into rows 62..93.
    for (int i = tid; i < NCHUNK * 16; i += 512) {
        int node = i >> 4, d4 = i & 15;
        int off = ((b * H_ + h) * NCHUNK + node) * 16 + d4;
        sK[(62 + node) * 16 + d4] = g_L6K4[off];
        sV[(62 + node) * 16 + d4] = g_L6V4[off];
    }
    __syncthreads();

    // Round 1: L1 (32, children = global leaves) + L7 (16, children = L6 rows).
    for (int t = halfIdx; t < 48; t += 32) {
        if (t < 32) {
            float4 Ko, Vo;
            parent_mix_f4(leafK[(2 * t) * LS + c16], leafK[(2 * t + 1) * LS + c16],
                          leafV[(2 * t) * LS + c16], leafV[(2 * t + 1) * LS + c16],
                          hmask, Ko, Vo);
            sK[t * 16 + c16] = Ko;
            sV[t * 16 + c16] = Vo;
        } else {
            int j = t - 32;
            mix_rows(sK, sV, 62 + 2 * j, 94 + j, c16, hmask);
        }
    }
    __syncthreads();
    // Round 2: L2 (16) + L8 (8)
    if (halfIdx < 24) {
        if (halfIdx < 16) mix_rows(sK, sV, 0 + 2 * halfIdx, 32 + halfIdx, c16, hmask);
        else { int j = halfIdx - 16; mix_rows(sK, sV, 94 + 2 * j, 110 + j, c16, hmask); }
    }
    __syncthreads();
    // Round 3: L3 (8) + L9 (4)
    if (halfIdx < 12) {
        if (halfIdx < 8) mix_rows(sK, sV, 32 + 2 * halfIdx, 48 + halfIdx, c16, hmask);
        else { int j = halfIdx - 8; mix_rows(sK, sV, 110 + 2 * j, 118 + j, c16, hmask); }
    }
    __syncthreads();
    // Round 4: L4 (4) + L10 (2)
    if (halfIdx < 6) {
        if (halfIdx < 4) mix_rows(sK, sV, 48 + 2 * halfIdx, 56 + halfIdx, c16, hmask);
        else { int j = halfIdx - 4; mix_rows(sK, sV, 118 + 2 * j, 122 + j, c16, hmask); }
    }
    __syncthreads();
    // Round 5: L5 (2)
    if (halfIdx < 2) mix_rows(sK, sV, 56 + 2 * halfIdx, 60 + halfIdx, c16, hmask);
    __syncthreads();

    // ---- Attention: 8-lane groups, 4 queries per warp, 64 per block ----
    const int baseL[11] = {0, 0, 1024, 1536, 1792, 1920, 1984, 2016, 2032, 2040, 2044};
    const int rowB[11]  = {0, 0, 32, 48, 56, 60, 62, 94, 110, 118, 122};

    int g  = lane >> 3;          // group 0..3
    int l8 = lane & 7;           // lane within group
    int qq = (warp << 2) | g;    // query 0..63 within chunk
    int n  = c * CHUNK + qq;

    // Levels >=2 smem rows + causal mask bits (all entries valid for N=2048).
    int row[NCOLS];
    unsigned maskbits = 0u;
    int ncur = n ^ 1;                    // lvl-1 entry: sibling leaf (global)
    if ((n & 1) == 0) maskbits |= 2u;    // pair(n) < n^1 when n even
#pragma unroll
    for (int lvl = 2; lvl < NCOLS; lvl++) {
        int pair = (ncur >> 1) + N_;
        int nnext = pair ^ 1;
        int L = lvl - 1;
        int jL = nnext - N_ - baseL[L];
        row[lvl] = rowB[L] + jL - ((L <= 5) ? (c << (6 - L)) : 0);
        if (pair < nnext) maskbits |= (1u << lvl);
        ncur = nnext;
    }

    int qbase = ((b * N_ + n) * H_ + h) * 16;
    float4 qa = Q4[qbase + l8];
    float4 qb = Q4[qbase + l8 + 8];

    float s[NCOLS];
    s[0] = dot4(qa, leafK[qq * LS + l8])       + dot4(qb, leafK[qq * LS + l8 + 8]);
    s[1] = dot4(qa, leafK[(qq ^ 1) * LS + l8]) + dot4(qb, leafK[(qq ^ 1) * LS + l8 + 8]);
#pragma unroll
    for (int l = 2; l < NCOLS; l++)
        s[l] = dot4(qa, sK[row[l] * 16 + l8]) + dot4(qb, sK[row[l] * 16 + l8 + 8]);

#pragma unroll
    for (int l = 0; l < NCOLS; l++)
        s[l] = octReduce(s[l]) * SCALE;

    float m = -INFINITY;
#pragma unroll
    for (int l = 0; l < NCOLS; l++)
        if (!((maskbits >> l) & 1u)) m = fmaxf(m, s[l]);

    float sum = 0.0f;
#pragma unroll
    for (int l = 0; l < NCOLS; l++) {
        float w = ((maskbits >> l) & 1u) ? 0.0f : __expf(s[l] - m);
        s[l] = w;
        sum += w;
    }
    float inv = 1.0f / sum;

    float4 oa = make_float4(0.f, 0.f, 0.f, 0.f);
    float4 ob = make_float4(0.f, 0.f, 0.f, 0.f);
    {
        float4 v0a = leafV[qq * LS + l8],       v0b = leafV[qq * LS + l8 + 8];
        float4 v1a = leafV[(qq ^ 1) * LS + l8], v1b = leafV[(qq ^ 1) * LS + l8 + 8];
        oa.x = s[0] * v0a.x + s[1] * v1a.x;  oa.y = s[0] * v0a.y + s[1] * v1a.y;
        oa.z = s[0] * v0a.z + s[1] * v1a.z;  oa.w = s[0] * v0a.w + s[1] * v1a.w;
        ob.x = s[0] * v0b.x + s[1] * v1b.x;  ob.y = s[0] * v0b.y + s[1] * v1b.y;
        ob.z = s[0] * v0b.z + s[1] * v1b.z;  ob.w = s[0] * v0b.w + s[1] * v1b.w;
    }
#pragma unroll
    for (int l = 2; l < NCOLS; l++) {
        float4 va = sV[row[l] * 16 + l8];
        float4 vb = sV[row[l] * 16 + l8 + 8];
        oa.x += s[l] * va.x;  oa.y += s[l] * va.y;
        oa.z += s[l] * va.z;  oa.w += s[l] * va.w;
        ob.x += s[l] * vb.x;  ob.y += s[l] * vb.y;
        ob.z += s[l] * vb.z;  ob.w += s[l] * vb.w;
    }
    out4[qbase + l8]     = make_float4(oa.x * inv, oa.y * inv, oa.z * inv, oa.w * inv);
    out4[qbase + l8 + 8] = make_float4(ob.x * inv, ob.y * inv, ob.z * inv, ob.w * inv);
}

extern "C" void kernel_launch(void* const* d_in, const int* in_sizes, int n_in,
                              void* d_out, int out_size)
{
    const float* Q = (const float*)d_in[0];
    const float* K = (const float*)d_in[1];
    const float* V = (const float*)d_in[2];
    float* out = (float*)d_out;

    const int smemBytes = 2 * ROWS_T * 16 * (int)sizeof(float4);   // 63488 B
    static int attrSet = 0;
    if (!attrSet) {
        cudaFuncSetAttribute(fused_attn, cudaFuncAttributeMaxDynamicSharedMemorySize, smemBytes);
        attrSet = 1;
    }

    build_chunk_root<<<B_ * H_ * NCHUNK, 512>>>(K, V);
    fused_attn<<<B_ * H_ * NCHUNK, 512, smemBytes>>>(Q, K, V, out);
}